// round 2
// baseline (speedup 1.0000x reference)
#include <cuda_runtime.h>
#include <cstdint>

// Problem constants
#define Bc    2
#define Nc    128
#define Sc    4
#define DGc   8
#define CINc  4
#define COUTc 8
#define HIDc  32

// Shared-memory weight layout (float offsets)
#define KYW1 0        // (4,32,2)   256
#define KYB1 256      // (4,32)     128
#define KYW2 384      // (4,32,32)  4096
#define KYB2 4480     // (4,32)     128
#define KYW3 4608     // (4,1,32)   128
#define KYB3 4736     // (4,1)      4
#define KGW1 4740     // (4,32,8)   1024
#define KGB1 5764     // (4,32)     128
#define KGW2 5892     // (4,32,32)  4096
#define KGB2 9988     // (4,32)     128
#define KGW3 10116    // (4,1,32)   128
#define KGB3 10244    // (4,1)      4
#define WOUT 10248    // (8,4)      32
#define SWTOT 10280

__device__ __forceinline__ float silu_f(float x) {
    // x * sigmoid(x) = x / (1 + e^-x); MUFU.EX2 + MUFU.RCP
    float e = __expf(-x);
    return __fdividef(x, 1.0f + e);
}

__global__ __launch_bounds__(512, 1)
void ema_kernel(const float* __restrict__ g,
                const float* __restrict__ f,
                const int* __restrict__ mask,          // bool canonicalized to int32
                const float* __restrict__ kyW1, const float* __restrict__ kyb1,
                const float* __restrict__ kyW2, const float* __restrict__ kyb2,
                const float* __restrict__ kyW3, const float* __restrict__ kyb3,
                const float* __restrict__ kgW1, const float* __restrict__ kgb1,
                const float* __restrict__ kgW2, const float* __restrict__ kgb2,
                const float* __restrict__ kgW3, const float* __restrict__ kgb3,
                const float* __restrict__ wout,
                float* __restrict__ out)
{
    __shared__ __align__(16) float sw[SWTOT];
    __shared__ float sred[16][8];

    const int tid = threadIdx.x;

    // ---- stage all weights into shared memory ----
    {
        for (int idx = tid; idx < 256;  idx += 512) sw[KYW1 + idx] = kyW1[idx];
        for (int idx = tid; idx < 128;  idx += 512) sw[KYB1 + idx] = kyb1[idx];
        for (int idx = tid; idx < 4096; idx += 512) sw[KYW2 + idx] = kyW2[idx];
        for (int idx = tid; idx < 128;  idx += 512) sw[KYB2 + idx] = kyb2[idx];
        for (int idx = tid; idx < 128;  idx += 512) sw[KYW3 + idx] = kyW3[idx];
        for (int idx = tid; idx < 4;    idx += 512) sw[KYB3 + idx] = kyb3[idx];
        for (int idx = tid; idx < 1024; idx += 512) sw[KGW1 + idx] = kgW1[idx];
        for (int idx = tid; idx < 128;  idx += 512) sw[KGB1 + idx] = kgb1[idx];
        for (int idx = tid; idx < 4096; idx += 512) sw[KGW2 + idx] = kgW2[idx];
        for (int idx = tid; idx < 128;  idx += 512) sw[KGB2 + idx] = kgb2[idx];
        for (int idx = tid; idx < 128;  idx += 512) sw[KGW3 + idx] = kgW3[idx];
        for (int idx = tid; idx < 4;    idx += 512) sw[KGB3 + idx] = kgb3[idx];
        for (int idx = tid; idx < 32;   idx += 512) sw[WOUT + idx] = wout[idx];
    }
    __syncthreads();

    // ---- decode query (b, i, s) from blockIdx ----
    const int bid = blockIdx.x;
    const int b   = bid >> 9;        // / (N*S) = /512
    const int rem = bid & 511;
    const int i   = rem >> 2;        // / S
    const int s   = rem & 3;         // % S

    // query f values (all channels)
    float fq[CINc];
    {
        const float* fqp = f + (((size_t)b * Nc + i) * Sc + s) * CINc;
        float4 v = *reinterpret_cast<const float4*>(fqp);
        fq[0] = v.x; fq[1] = v.y; fq[2] = v.z; fq[3] = v.w;
    }

    // ---- this thread's key (j, t) ----
    const int j = tid >> 2;
    const int t = tid & 3;

    // g[b,i,j,s,t,0..7]
    float gv[DGc];
    {
        const float* gp = g + ((((((size_t)b * Nc + i) * Nc + j) * Sc + s) * Sc) + t) * DGc;
        float4 g0 = *reinterpret_cast<const float4*>(gp);
        float4 g1 = *reinterpret_cast<const float4*>(gp + 4);
        gv[0] = g0.x; gv[1] = g0.y; gv[2] = g0.z; gv[3] = g0.w;
        gv[4] = g1.x; gv[5] = g1.y; gv[6] = g1.z; gv[7] = g1.w;
    }

    const bool mk = mask[((size_t)b * Nc + j) * Sc + t] != 0;

    float fk[CINc];
    {
        const float* fkp = f + (((size_t)b * Nc + j) * Sc + t) * CINc;
        float4 v = *reinterpret_cast<const float4*>(fkp);
        fk[0] = v.x; fk[1] = v.y; fk[2] = v.z; fk[3] = v.w;
    }

    float num[CINc], den[CINc];

    // ---- per-channel MLPs ----
    #pragma unroll 1
    for (int c = 0; c < CINc; ++c) {
        const float fkc = fk[c];
        const float fqc = fq[c];

        float h1[HIDc];
        float h2[HIDc];

        // === MLP_y ===
        {   // layer 1: 2 -> 32
            const float* W1 = &sw[KYW1 + c * HIDc * 2];
            const float* B1 = &sw[KYB1 + c * HIDc];
            #pragma unroll
            for (int h = 0; h < HIDc; ++h) {
                float a = fmaf(fkc, W1[2*h], fmaf(fqc, W1[2*h+1], B1[h]));
                h1[h] = silu_f(a);
            }
        }
        {   // layer 2: 32 -> 32
            const float* B2 = &sw[KYB2 + c * HIDc];
            #pragma unroll
            for (int o = 0; o < HIDc; ++o) {
                const float4* W = reinterpret_cast<const float4*>(&sw[KYW2 + c * HIDc * HIDc + o * HIDc]);
                float a = B2[o];
                #pragma unroll
                for (int q = 0; q < HIDc/4; ++q) {
                    float4 w = W[q];
                    a = fmaf(h1[4*q+0], w.x, a);
                    a = fmaf(h1[4*q+1], w.y, a);
                    a = fmaf(h1[4*q+2], w.z, a);
                    a = fmaf(h1[4*q+3], w.w, a);
                }
                h2[o] = silu_f(a);
            }
        }
        float ky;
        {   // layer 3: 32 -> 1
            const float4* W = reinterpret_cast<const float4*>(&sw[KYW3 + c * HIDc]);
            float a = sw[KYB3 + c];
            #pragma unroll
            for (int q = 0; q < HIDc/4; ++q) {
                float4 w = W[q];
                a = fmaf(h2[4*q+0], w.x, a);
                a = fmaf(h2[4*q+1], w.y, a);
                a = fmaf(h2[4*q+2], w.z, a);
                a = fmaf(h2[4*q+3], w.w, a);
            }
            ky = silu_f(a);
        }

        // === MLP_g ===
        {   // layer 1: 8 -> 32
            const float* B1 = &sw[KGB1 + c * HIDc];
            #pragma unroll
            for (int h = 0; h < HIDc; ++h) {
                const float4* W = reinterpret_cast<const float4*>(&sw[KGW1 + c * HIDc * DGc + h * DGc]);
                float4 w0 = W[0], w1 = W[1];
                float a = B1[h];
                a = fmaf(gv[0], w0.x, a);
                a = fmaf(gv[1], w0.y, a);
                a = fmaf(gv[2], w0.z, a);
                a = fmaf(gv[3], w0.w, a);
                a = fmaf(gv[4], w1.x, a);
                a = fmaf(gv[5], w1.y, a);
                a = fmaf(gv[6], w1.z, a);
                a = fmaf(gv[7], w1.w, a);
                h1[h] = silu_f(a);
            }
        }
        {   // layer 2: 32 -> 32
            const float* B2 = &sw[KGB2 + c * HIDc];
            #pragma unroll
            for (int o = 0; o < HIDc; ++o) {
                const float4* W = reinterpret_cast<const float4*>(&sw[KGW2 + c * HIDc * HIDc + o * HIDc]);
                float a = B2[o];
                #pragma unroll
                for (int q = 0; q < HIDc/4; ++q) {
                    float4 w = W[q];
                    a = fmaf(h1[4*q+0], w.x, a);
                    a = fmaf(h1[4*q+1], w.y, a);
                    a = fmaf(h1[4*q+2], w.z, a);
                    a = fmaf(h1[4*q+3], w.w, a);
                }
                h2[o] = silu_f(a);
            }
        }
        float kg;
        {   // layer 3: 32 -> 1
            const float4* W = reinterpret_cast<const float4*>(&sw[KGW3 + c * HIDc]);
            float a = sw[KGB3 + c];
            #pragma unroll
            for (int q = 0; q < HIDc/4; ++q) {
                float4 w = W[q];
                a = fmaf(h2[4*q+0], w.x, a);
                a = fmaf(h2[4*q+1], w.y, a);
                a = fmaf(h2[4*q+2], w.z, a);
                a = fmaf(h2[4*q+3], w.w, a);
            }
            kg = silu_f(a);
        }

        const float kv = ky + kg;
        const float e  = mk ? __expf(kv) : 0.0f;
        den[c] = e;
        num[c] = e * fkc;
    }

    // ---- reduce 8 accumulators over 512 threads ----
    #pragma unroll
    for (int c = 0; c < CINc; ++c) {
        #pragma unroll
        for (int off = 16; off > 0; off >>= 1) {
            num[c] += __shfl_xor_sync(0xFFFFFFFFu, num[c], off);
            den[c] += __shfl_xor_sync(0xFFFFFFFFu, den[c], off);
        }
    }
    const int wid = tid >> 5;
    const int lid = tid & 31;
    if (lid == 0) {
        #pragma unroll
        for (int c = 0; c < CINc; ++c) {
            sred[wid][c]     = num[c];
            sred[wid][4 + c] = den[c];
        }
    }
    __syncthreads();

    // ---- epilogue: cf = (f + num/den) * mask_q ; out = cf @ w_out.T ----
    if (tid < COUTc) {
        const int o = tid;
        const float mq = (mask[((size_t)b * Nc + i) * Sc + s] != 0) ? 1.0f : 0.0f;
        float acc = 0.0f;
        #pragma unroll
        for (int c = 0; c < CINc; ++c) {
            float n = 0.0f, d = 0.0f;
            #pragma unroll
            for (int w = 0; w < 16; ++w) {
                n += sred[w][c];
                d += sred[w][4 + c];
            }
            const float cf = (fq[c] + n / d) * mq;
            acc = fmaf(cf, sw[WOUT + o * CINc + c], acc);
        }
        out[(((size_t)b * Nc + i) * Sc + s) * COUTc + o] = acc;
    }
}

extern "C" void kernel_launch(void* const* d_in, const int* in_sizes, int n_in,
                              void* d_out, int out_size)
{
    const float* g    = (const float*)d_in[0];
    const float* f    = (const float*)d_in[1];
    const int*   mask = (const int*)d_in[2];
    const float* kyW1 = (const float*)d_in[3];
    const float* kyb1 = (const float*)d_in[4];
    const float* kyW2 = (const float*)d_in[5];
    const float* kyb2 = (const float*)d_in[6];
    const float* kyW3 = (const float*)d_in[7];
    const float* kyb3 = (const float*)d_in[8];
    const float* kgW1 = (const float*)d_in[9];
    const float* kgb1 = (const float*)d_in[10];
    const float* kgW2 = (const float*)d_in[11];
    const float* kgb2 = (const float*)d_in[12];
    const float* kgW3 = (const float*)d_in[13];
    const float* kgb3 = (const float*)d_in[14];
    const float* wout = (const float*)d_in[15];
    float* out = (float*)d_out;

    ema_kernel<<<Bc * Nc * Sc, 512>>>(g, f, mask,
                                      kyW1, kyb1, kyW2, kyb2, kyW3, kyb3,
                                      kgW1, kgb1, kgW2, kgb2, kgW3, kgb3,
                                      wout, out);
}

// round 3
// speedup vs baseline: 1.0730x; 1.0730x over previous
#include <cuda_runtime.h>
#include <cstdint>

// Problem constants
#define Bc    2
#define Nc    128
#define Sc    4
#define DGc   8
#define CINc  4
#define COUTc 8
#define HIDc  32

// Shared-memory weight layout (float offsets). Matrices marked (packed) are
// stored transposed-by-input: dst[k*32 + o] = W[o][k], so outputs are
// contiguous and LDS.128 yields two f32x2 weight pairs.
#define KYW1 0        // packed (4)[2][32]   256
#define KYB1 256      // natural (4,32)      128
#define KYW2 384      // packed (4)[32][32]  4096
#define KYB2 4480     // natural             128
#define KYW3 4608     // natural (4,32)      128
#define KYB3 4736     // (4)                 4
#define KGW1 4740     // packed (4)[8][32]   1024
#define KGB1 5764     // natural             128
#define KGW2 5892     // packed (4)[32][32]  4096
#define KGB2 9988     // natural             128
#define KGW3 10116    // natural             128
#define KGB3 10244    // (4)                 4
#define WOUT 10248    // (8,4)               32
#define SWTOT 10280

typedef unsigned long long u64;

__device__ __forceinline__ u64 pk2(float lo, float hi) {
    u64 r; asm("mov.b64 %0, {%1, %2};" : "=l"(r) : "f"(lo), "f"(hi)); return r;
}
__device__ __forceinline__ void upk2(u64 v, float& lo, float& hi) {
    asm("mov.b64 {%0, %1}, %2;" : "=f"(lo), "=f"(hi) : "l"(v));
}
__device__ __forceinline__ u64 fma2(u64 a, u64 b, u64 c) {
    u64 d; asm("fma.rn.f32x2 %0, %1, %2, %3;" : "=l"(d) : "l"(a), "l"(b), "l"(c)); return d;
}
__device__ __forceinline__ u64 mul2(u64 a, u64 b) {
    u64 d; asm("mul.rn.f32x2 %0, %1, %2;" : "=l"(d) : "l"(a), "l"(b)); return d;
}
__device__ __forceinline__ u64 add2(u64 a, u64 b) {
    u64 d; asm("add.rn.f32x2 %0, %1, %2;" : "=l"(d) : "l"(a), "l"(b)); return d;
}
__device__ __forceinline__ float ex2f(float x) {
    float r; asm("ex2.approx.f32 %0, %1;" : "=f"(r) : "f"(x)); return r;
}
__device__ __forceinline__ float rcpf(float x) {
    float r; asm("rcp.approx.f32 %0, %1;" : "=f"(r) : "f"(x)); return r;
}

// packed silu on 2 elements: 3 fma-pipe ops + 4 MUFU (vs 6 + 4 scalar)
__device__ __forceinline__ u64 silu2(u64 x2) {
    u64 t = mul2(x2, pk2(-1.4426950408889634f, -1.4426950408889634f));
    float t0, t1; upk2(t, t0, t1);
    u64 e = pk2(ex2f(t0), ex2f(t1));
    u64 d = add2(e, pk2(1.0f, 1.0f));
    float d0, d1; upk2(d, d0, d1);
    u64 r = pk2(rcpf(d0), rcpf(d1));
    return mul2(x2, r);
}

__device__ __forceinline__ float silu_f(float x) {
    float e = ex2f(-1.4426950408889634f * x);
    return x * rcpf(1.0f + e);
}
__device__ __forceinline__ float expf_f(float x) {
    return ex2f(1.4426950408889634f * x);
}

__global__ __launch_bounds__(256)
void ema_kernel(const float* __restrict__ g,
                const float* __restrict__ f,
                const int* __restrict__ mask,
                const float* __restrict__ kyW1, const float* __restrict__ kyb1,
                const float* __restrict__ kyW2, const float* __restrict__ kyb2,
                const float* __restrict__ kyW3, const float* __restrict__ kyb3,
                const float* __restrict__ kgW1, const float* __restrict__ kgb1,
                const float* __restrict__ kgW2, const float* __restrict__ kgb2,
                const float* __restrict__ kgW3, const float* __restrict__ kgb3,
                const float* __restrict__ wout,
                float* __restrict__ out)
{
    __shared__ __align__(16) float sw[SWTOT];
    __shared__ float sred[8][8];

    const int tid = threadIdx.x;

    // ---- stage weights, transposing the matvec matrices ----
    {
        // kyW1 (4,32,2): dst[c*64 + k*32 + o]
        for (int idx = tid; idx < 256; idx += 256) {
            int c = idx >> 6, r = idx & 63, o = r >> 1, k = r & 1;
            sw[KYW1 + c * 64 + k * 32 + o] = kyW1[idx];
        }
        // kyW2 / kgW2 (4,32,32): dst[c*1024 + k*32 + o]
        for (int idx = tid; idx < 4096; idx += 256) {
            int c = idx >> 10, r = idx & 1023, o = r >> 5, k = r & 31;
            sw[KYW2 + c * 1024 + k * 32 + o] = kyW2[idx];
            sw[KGW2 + c * 1024 + k * 32 + o] = kgW2[idx];
        }
        // kgW1 (4,32,8): dst[c*256 + k*32 + o]
        for (int idx = tid; idx < 1024; idx += 256) {
            int c = idx >> 8, r = idx & 255, o = r >> 3, k = r & 7;
            sw[KGW1 + c * 256 + k * 32 + o] = kgW1[idx];
        }
        for (int idx = tid; idx < 128; idx += 256) {
            sw[KYB1 + idx] = kyb1[idx];
            sw[KYB2 + idx] = kyb2[idx];
            sw[KYW3 + idx] = kyW3[idx];
            sw[KGB1 + idx] = kgb1[idx];
            sw[KGB2 + idx] = kgb2[idx];
            sw[KGW3 + idx] = kgW3[idx];
        }
        if (tid < 4) { sw[KYB3 + tid] = kyb3[tid]; sw[KGB3 + tid] = kgb3[tid]; }
        if (tid < 32) sw[WOUT + tid] = wout[tid];
    }
    __syncthreads();

    // ---- decode query (b, i, s) ----
    const int bid = blockIdx.x;
    const int b   = bid >> 9;
    const int rem = bid & 511;
    const int i   = rem >> 2;
    const int s   = rem & 3;

    float fq[CINc];
    {
        const float* fqp = f + (((size_t)b * Nc + i) * Sc + s) * CINc;
        float4 v = *reinterpret_cast<const float4*>(fqp);
        fq[0] = v.x; fq[1] = v.y; fq[2] = v.z; fq[3] = v.w;
    }

    // ---- two keys per thread: (j0,t) and (j0+64,t) ----
    const int j0 = tid >> 2;
    const int t  = tid & 3;
    const int j1 = j0 + 64;

    float gvA[DGc], gvB[DGc];
    {
        const float* gp = g + ((((((size_t)b * Nc + i) * Nc + j0) * Sc + s) * Sc) + t) * DGc;
        float4 g0 = *reinterpret_cast<const float4*>(gp);
        float4 g1 = *reinterpret_cast<const float4*>(gp + 4);
        gvA[0]=g0.x; gvA[1]=g0.y; gvA[2]=g0.z; gvA[3]=g0.w;
        gvA[4]=g1.x; gvA[5]=g1.y; gvA[6]=g1.z; gvA[7]=g1.w;
        const float* gp2 = gp + (size_t)64 * Sc * Sc * DGc;
        float4 h0 = *reinterpret_cast<const float4*>(gp2);
        float4 h1 = *reinterpret_cast<const float4*>(gp2 + 4);
        gvB[0]=h0.x; gvB[1]=h0.y; gvB[2]=h0.z; gvB[3]=h0.w;
        gvB[4]=h1.x; gvB[5]=h1.y; gvB[6]=h1.z; gvB[7]=h1.w;
    }

    const bool mkA = mask[((size_t)b * Nc + j0) * Sc + t] != 0;
    const bool mkB = mask[((size_t)b * Nc + j1) * Sc + t] != 0;

    float fkA[CINc], fkB[CINc];
    {
        const float* p0 = f + (((size_t)b * Nc + j0) * Sc + t) * CINc;
        float4 v = *reinterpret_cast<const float4*>(p0);
        fkA[0]=v.x; fkA[1]=v.y; fkA[2]=v.z; fkA[3]=v.w;
        const float* p1 = f + (((size_t)b * Nc + j1) * Sc + t) * CINc;
        float4 w = *reinterpret_cast<const float4*>(p1);
        fkB[0]=w.x; fkB[1]=w.y; fkB[2]=w.z; fkB[3]=w.w;
    }

    float num[CINc], den[CINc];

    #pragma unroll 1
    for (int c = 0; c < CINc; ++c) {
        float kyA = 0.f, kyB = 0.f, kgA = 0.f, kgB = 0.f;

        #pragma unroll 1
        for (int m = 0; m < 2; ++m) {
            u64 acc0[16], acc1[16];      // packed output pairs, pos A / pos B
            float hA[HIDc], hB[HIDc];    // layer-1 activations (scalar)

            // ================= layer 1 =================
            if (m == 0) {
                const float* w  = &sw[KYW1 + c * 64];
                const float* bb = &sw[KYB1 + c * HIDc];
                const u64 fqd  = pk2(fq[c],  fq[c]);
                const u64 fkAd = pk2(fkA[c], fkA[c]);
                const u64 fkBd = pk2(fkB[c], fkB[c]);
                #pragma unroll
                for (int q = 0; q < 8; ++q) {
                    ulonglong2 w0 = *reinterpret_cast<const ulonglong2*>(&w[4*q]);       // k=0 (f_key)
                    ulonglong2 w1 = *reinterpret_cast<const ulonglong2*>(&w[32 + 4*q]);  // k=1 (f_query)
                    u64 b0 = *reinterpret_cast<const u64*>(&bb[4*q]);
                    u64 b1 = *reinterpret_cast<const u64*>(&bb[4*q + 2]);
                    u64 t0 = fma2(fqd, w1.x, b0);
                    u64 t1 = fma2(fqd, w1.y, b1);
                    acc0[2*q]   = fma2(fkAd, w0.x, t0);
                    acc0[2*q+1] = fma2(fkAd, w0.y, t1);
                    acc1[2*q]   = fma2(fkBd, w0.x, t0);
                    acc1[2*q+1] = fma2(fkBd, w0.y, t1);
                }
            } else {
                const float* w  = &sw[KGW1 + c * 256];
                const float* bb = &sw[KGB1 + c * HIDc];
                #pragma unroll
                for (int q = 0; q < 8; ++q) {
                    u64 b0 = *reinterpret_cast<const u64*>(&bb[4*q]);
                    u64 b1 = *reinterpret_cast<const u64*>(&bb[4*q + 2]);
                    acc0[2*q] = b0; acc0[2*q+1] = b1;
                    acc1[2*q] = b0; acc1[2*q+1] = b1;
                }
                #pragma unroll
                for (int k = 0; k < DGc; ++k) {
                    const u64 gAd = pk2(gvA[k], gvA[k]);
                    const u64 gBd = pk2(gvB[k], gvB[k]);
                    const float* wk = &w[k * 32];
                    #pragma unroll
                    for (int q = 0; q < 8; ++q) {
                        ulonglong2 wv = *reinterpret_cast<const ulonglong2*>(&wk[4*q]);
                        acc0[2*q]   = fma2(gAd, wv.x, acc0[2*q]);
                        acc0[2*q+1] = fma2(gAd, wv.y, acc0[2*q+1]);
                        acc1[2*q]   = fma2(gBd, wv.x, acc1[2*q]);
                        acc1[2*q+1] = fma2(gBd, wv.y, acc1[2*q+1]);
                    }
                }
            }
            // silu -> scalar activations
            #pragma unroll
            for (int p = 0; p < 16; ++p) {
                u64 s0 = silu2(acc0[p]); upk2(s0, hA[2*p], hA[2*p+1]);
                u64 s1 = silu2(acc1[p]); upk2(s1, hB[2*p], hB[2*p+1]);
            }

            // ================= layer 2 (32 -> 32) =================
            {
                const float* w2 = &sw[(m ? KGW2 : KYW2) + c * 1024];
                const float* b2 = &sw[(m ? KGB2 : KYB2) + c * HIDc];
                #pragma unroll
                for (int q = 0; q < 8; ++q) {
                    u64 b0 = *reinterpret_cast<const u64*>(&b2[4*q]);
                    u64 b1 = *reinterpret_cast<const u64*>(&b2[4*q + 2]);
                    acc0[2*q] = b0; acc0[2*q+1] = b1;
                    acc1[2*q] = b0; acc1[2*q+1] = b1;
                }
                #pragma unroll
                for (int k = 0; k < HIDc; ++k) {
                    const u64 hAd = pk2(hA[k], hA[k]);
                    const u64 hBd = pk2(hB[k], hB[k]);
                    const float* wk = &w2[k * 32];
                    #pragma unroll
                    for (int q = 0; q < 8; ++q) {
                        ulonglong2 wv = *reinterpret_cast<const ulonglong2*>(&wk[4*q]);
                        acc0[2*q]   = fma2(hAd, wv.x, acc0[2*q]);
                        acc0[2*q+1] = fma2(hAd, wv.y, acc0[2*q+1]);
                        acc1[2*q]   = fma2(hBd, wv.x, acc1[2*q]);
                        acc1[2*q+1] = fma2(hBd, wv.y, acc1[2*q+1]);
                    }
                }
                // silu, keep packed
                #pragma unroll
                for (int p = 0; p < 16; ++p) {
                    acc0[p] = silu2(acc0[p]);
                    acc1[p] = silu2(acc1[p]);
                }
            }

            // ================= layer 3 (32 -> 1) =================
            {
                const float* w3 = &sw[(m ? KGW3 : KYW3) + c * HIDc];
                const float b3  = sw[(m ? KGB3 : KYB3) + c];
                u64 t0 = pk2(0.f, 0.f), t1 = pk2(0.f, 0.f);
                #pragma unroll
                for (int q = 0; q < 8; ++q) {
                    ulonglong2 wv = *reinterpret_cast<const ulonglong2*>(&w3[4*q]);
                    t0 = fma2(acc0[2*q],   wv.x, t0);
                    t0 = fma2(acc0[2*q+1], wv.y, t0);
                    t1 = fma2(acc1[2*q],   wv.x, t1);
                    t1 = fma2(acc1[2*q+1], wv.y, t1);
                }
                float a0, a1, c0, c1;
                upk2(t0, a0, a1); upk2(t1, c0, c1);
                float rA = silu_f(a0 + a1 + b3);
                float rB = silu_f(c0 + c1 + b3);
                if (m == 0) { kyA = rA; kyB = rB; }
                else        { kgA = rA; kgB = rB; }
            }
        }

        const float eA = mkA ? expf_f(kyA + kgA) : 0.0f;
        const float eB = mkB ? expf_f(kyB + kgB) : 0.0f;
        den[c] = eA + eB;
        num[c] = eA * fkA[c] + eB * fkB[c];
    }

    // ---- reduce over 256 threads (8 warps) ----
    #pragma unroll
    for (int c = 0; c < CINc; ++c) {
        #pragma unroll
        for (int off = 16; off > 0; off >>= 1) {
            num[c] += __shfl_xor_sync(0xFFFFFFFFu, num[c], off);
            den[c] += __shfl_xor_sync(0xFFFFFFFFu, den[c], off);
        }
    }
    const int wid = tid >> 5;
    const int lid = tid & 31;
    if (lid == 0) {
        #pragma unroll
        for (int c = 0; c < CINc; ++c) {
            sred[wid][c]     = num[c];
            sred[wid][4 + c] = den[c];
        }
    }
    __syncthreads();

    if (tid < COUTc) {
        const int o = tid;
        const float mq = (mask[((size_t)b * Nc + i) * Sc + s] != 0) ? 1.0f : 0.0f;
        float acc = 0.0f;
        #pragma unroll
        for (int c = 0; c < CINc; ++c) {
            float n = 0.0f, d = 0.0f;
            #pragma unroll
            for (int w = 0; w < 8; ++w) {
                n += sred[w][c];
                d += sred[w][4 + c];
            }
            const float cf = (fq[c] + n / d) * mq;
            acc = fmaf(cf, sw[WOUT + o * CINc + c], acc);
        }
        out[(((size_t)b * Nc + i) * Sc + s) * COUTc + o] = acc;
    }
}

extern "C" void kernel_launch(void* const* d_in, const int* in_sizes, int n_in,
                              void* d_out, int out_size)
{
    const float* g    = (const float*)d_in[0];
    const float* f    = (const float*)d_in[1];
    const int*   mask = (const int*)d_in[2];
    const float* kyW1 = (const float*)d_in[3];
    const float* kyb1 = (const float*)d_in[4];
    const float* kyW2 = (const float*)d_in[5];
    const float* kyb2 = (const float*)d_in[6];
    const float* kyW3 = (const float*)d_in[7];
    const float* kyb3 = (const float*)d_in[8];
    const float* kgW1 = (const float*)d_in[9];
    const float* kgb1 = (const float*)d_in[10];
    const float* kgW2 = (const float*)d_in[11];
    const float* kgb2 = (const float*)d_in[12];
    const float* kgW3 = (const float*)d_in[13];
    const float* kgb3 = (const float*)d_in[14];
    const float* wout = (const float*)d_in[15];
    float* out = (float*)d_out;

    ema_kernel<<<Bc * Nc * Sc, 256>>>(g, f, mask,
                                      kyW1, kyb1, kyW2, kyb2, kyW3, kyb3,
                                      kgW1, kgb1, kgW2, kgb2, kgW3, kgb3,
                                      wout, out);
}